// round 2
// baseline (speedup 1.0000x reference)
#include <cuda_runtime.h>

#define SH 16
#define SW 16
#define SL 8
#define NCOEF 12
#define GRID_ELEMS (SH * SW * SL * NCOEF)   // 24576 floats = 96 KB
#define GRID_BYTES (GRID_ELEMS * 4)

__global__ void __launch_bounds__(256, 2)
bilateral_grid_kernel(const float* __restrict__ pixels,
                      const float* __restrict__ coords,
                      const float* __restrict__ grid,
                      float* __restrict__ out,
                      int N)
{
    extern __shared__ float sg[];

    // Cooperative fill of the 96 KB grid into shared memory (float4 vectorized).
    {
        const float4* g4 = reinterpret_cast<const float4*>(grid);
        float4* s4 = reinterpret_cast<float4*>(sg);
        #pragma unroll 4
        for (int i = threadIdx.x; i < GRID_ELEMS / 4; i += blockDim.x)
            s4[i] = g4[i];
    }
    __syncthreads();

    const int stride = gridDim.x * blockDim.x;
    for (int i = blockIdx.x * blockDim.x + threadIdx.x; i < N; i += stride) {
        // ---- load inputs (coalesced across the warp) ----
        const float r = pixels[3 * i + 0];
        const float g = pixels[3 * i + 1];
        const float b = pixels[3 * i + 2];
        const float2 c = reinterpret_cast<const float2*>(coords)[i];

        // ---- guide + grid coordinates ----
        const float guide = 0.2126f * r + 0.7152f * g + 0.0722f * b;
        float gx = fminf(fmaxf(c.x * (float)(SW - 1), 0.0f), (float)SW - 1.001f);
        float gy = fminf(fmaxf(c.y * (float)(SH - 1), 0.0f), (float)SH - 1.001f);
        float gcl = fminf(fmaxf(guide, 0.0f), 1.0f);
        float gz = fminf(fmaxf(gcl * (float)(SL - 1), 0.0f), (float)SL - 1.001f);

        const int x0 = (int)gx;
        const int y0 = (int)gy;
        const int z0 = (int)gz;
        const float fx = gx - (float)x0;
        const float fy = gy - (float)y0;
        const float fz = gz - (float)z0;

        // trilinear weights (8-corner weighted sum: fewer FMAs than nested lerp)
        const float wx0 = 1.0f - fx, wx1 = fx;
        const float wy0 = 1.0f - fy, wy1 = fy;
        const float wz0 = 1.0f - fz, wz1 = fz;

        float a0 = 0.f, a1 = 0.f, a2 = 0.f, a3 = 0.f;
        float a4 = 0.f, a5 = 0.f, a6 = 0.f, a7 = 0.f;
        float a8 = 0.f, a9 = 0.f, a10 = 0.f, a11 = 0.f;

        #pragma unroll
        for (int dy = 0; dy < 2; ++dy) {
            const float wyv = dy ? wy1 : wy0;
            const int yy = y0 + dy;
            #pragma unroll
            for (int dx = 0; dx < 2; ++dx) {
                const float wyx = wyv * (dx ? wx1 : wx0);
                const int base = (((yy * SW) + (x0 + dx)) * SL + z0) * NCOEF;
                // z0 and z1 corners are the 24 contiguous floats at base.
                #pragma unroll
                for (int dz = 0; dz < 2; ++dz) {
                    const float w = wyx * (dz ? wz1 : wz0);
                    const float4* p4 =
                        reinterpret_cast<const float4*>(sg + base + dz * NCOEF);
                    const float4 v0 = p4[0];
                    const float4 v1 = p4[1];
                    const float4 v2 = p4[2];
                    a0  += w * v0.x;  a1  += w * v0.y;
                    a2  += w * v0.z;  a3  += w * v0.w;
                    a4  += w * v1.x;  a5  += w * v1.y;
                    a6  += w * v1.z;  a7  += w * v1.w;
                    a8  += w * v2.x;  a9  += w * v2.y;
                    a10 += w * v2.z;  a11 += w * v2.w;
                }
            }
        }

        // affine transform: out = A[:, :3] @ rgb + A[:, 3]
        const float o0 = a0 * r + a1 * g + a2  * b + a3;
        const float o1 = a4 * r + a5 * g + a6  * b + a7;
        const float o2 = a8 * r + a9 * g + a10 * b + a11;

        out[3 * i + 0] = o0;
        out[3 * i + 1] = o1;
        out[3 * i + 2] = o2;
    }
}

extern "C" void kernel_launch(void* const* d_in, const int* in_sizes, int n_in,
                              void* d_out, int out_size)
{
    const float* pixels = (const float*)d_in[0];   // (B,H,W,3) f32
    const float* coords = (const float*)d_in[1];   // (B,H,W,2) f32
    const float* grid   = (const float*)d_in[2];   // (16,16,8,12) f32
    float* out = (float*)d_out;

    const int N = in_sizes[0] / 3;   // number of pixels

    cudaFuncSetAttribute(bilateral_grid_kernel,
                         cudaFuncAttributeMaxDynamicSharedMemorySize, GRID_BYTES);

    // 2 CTAs per SM (152 SMs on GB300) — each CTA fills smem once, then streams.
    const int blocks = 304;
    bilateral_grid_kernel<<<blocks, 256, GRID_BYTES>>>(pixels, coords, grid, out, N);
}

// round 6
// speedup vs baseline: 1.5520x; 1.5520x over previous
#include <cuda_runtime.h>
#include <cuda_fp16.h>

#define SH 16
#define SW 16
#define SL 8
#define NCOEF 12
#define GRID_ELEMS (SH * SW * SL * NCOEF)        // 24576
#define SMEM_BYTES (GRID_ELEMS * 2)              // 48 KB fp16

__device__ __forceinline__ __half2 as_h2(unsigned int u) {
    return *reinterpret_cast<__half2*>(&u);
}

__device__ __forceinline__ void process_pixel(
    const __half* __restrict__ sg,
    float r, float g, float b, float cxv, float cyv,
    float& o0, float& o1, float& o2)
{
    const float guide = 0.2126f * r + 0.7152f * g + 0.0722f * b;
    const float gx = fminf(fmaxf(cxv * (float)(SW - 1), 0.0f), (float)SW - 1.001f);
    const float gy = fminf(fmaxf(cyv * (float)(SH - 1), 0.0f), (float)SH - 1.001f);
    const float gcl = fminf(fmaxf(guide, 0.0f), 1.0f);
    const float gz = fminf(fmaxf(gcl * (float)(SL - 1), 0.0f), (float)SL - 1.001f);

    const int x0 = (int)gx;
    const int y0 = (int)gy;
    const int z0 = (int)gz;
    const float fx = gx - (float)x0;
    const float fy = gy - (float)y0;
    const float fz = gz - (float)z0;
    const float wx0 = 1.0f - fx, wy0 = 1.0f - fy, wz0 = 1.0f - fz;

    // index in halfs: ((y*SW + x)*SL + z) * NCOEF
    const int cell = ((y0 * SW + x0) * SL + z0) * NCOEF;

    __half2 acc0 = __float2half2_rn(0.f), acc1 = acc0, acc2 = acc0;
    __half2 acc3 = acc0, acc4 = acc0, acc5 = acc0;

    #pragma unroll
    for (int dy = 0; dy < 2; ++dy) {
        const float wyv = dy ? fy : wy0;
        #pragma unroll
        for (int dx = 0; dx < 2; ++dx) {
            const float wxy = wyv * (dx ? fx : wx0);
            const int idx = cell + dy * (SW * SL * NCOEF) + dx * (SL * NCOEF);
            // 48 bytes: z0's 12 halfs then z1's 12 halfs, 8B-aligned (idx*2 % 8 == 0)
            const uint2* p = reinterpret_cast<const uint2*>(sg + idx);
            const uint2 q0 = p[0];
            const uint2 q1 = p[1];
            const uint2 q2 = p[2];
            const uint2 q3 = p[3];
            const uint2 q4 = p[4];
            const uint2 q5 = p[5];

            const __half2 w0 = __float2half2_rn(wxy * wz0);
            const __half2 w1 = __float2half2_rn(wxy * fz);

            acc0 = __hfma2(w0, as_h2(q0.x), acc0);
            acc1 = __hfma2(w0, as_h2(q0.y), acc1);
            acc2 = __hfma2(w0, as_h2(q1.x), acc2);
            acc3 = __hfma2(w0, as_h2(q1.y), acc3);
            acc4 = __hfma2(w0, as_h2(q2.x), acc4);
            acc5 = __hfma2(w0, as_h2(q2.y), acc5);

            acc0 = __hfma2(w1, as_h2(q3.x), acc0);
            acc1 = __hfma2(w1, as_h2(q3.y), acc1);
            acc2 = __hfma2(w1, as_h2(q4.x), acc2);
            acc3 = __hfma2(w1, as_h2(q4.y), acc3);
            acc4 = __hfma2(w1, as_h2(q5.x), acc4);
            acc5 = __hfma2(w1, as_h2(q5.y), acc5);
        }
    }

    const float2 f0 = __half22float2(acc0);
    const float2 f1 = __half22float2(acc1);
    const float2 f2 = __half22float2(acc2);
    const float2 f3 = __half22float2(acc3);
    const float2 f4 = __half22float2(acc4);
    const float2 f5 = __half22float2(acc5);

    o0 = f0.x * r + f0.y * g + f1.x * b + f1.y;
    o1 = f2.x * r + f2.y * g + f3.x * b + f3.y;
    o2 = f4.x * r + f4.y * g + f5.x * b + f5.y;
}

__global__ void __launch_bounds__(256, 3)
bilateral_grid_h2_kernel(const float* __restrict__ pixels,
                         const float* __restrict__ coords,
                         const float* __restrict__ grid,
                         float* __restrict__ out,
                         int N)
{
    extern __shared__ __half sg[];

    // Convert fp32 grid -> fp16 in shared memory.
    {
        const float2* g2 = reinterpret_cast<const float2*>(grid);
        __half2* s2 = reinterpret_cast<__half2*>(sg);
        #pragma unroll 4
        for (int i = threadIdx.x; i < GRID_ELEMS / 2; i += 256)
            s2[i] = __float22half2_rn(g2[i]);
    }
    __syncthreads();

    const int nb = N >> 2;  // 4-pixel batches
    const int stride = gridDim.x * blockDim.x;
    const int tid0 = blockIdx.x * blockDim.x + threadIdx.x;

    for (int bix = tid0; bix < nb; bix += stride) {
        // 4 pixels: 12 floats of rgb, 8 floats of coords — fully vectorized.
        const float4 px0 = reinterpret_cast<const float4*>(pixels)[3 * bix + 0];
        const float4 px1 = reinterpret_cast<const float4*>(pixels)[3 * bix + 1];
        const float4 px2 = reinterpret_cast<const float4*>(pixels)[3 * bix + 2];
        const float4 cd0 = reinterpret_cast<const float4*>(coords)[2 * bix + 0];
        const float4 cd1 = reinterpret_cast<const float4*>(coords)[2 * bix + 1];

        const float rr[4] = {px0.x, px0.w, px1.z, px2.y};
        const float gg[4] = {px0.y, px1.x, px1.w, px2.z};
        const float bb[4] = {px0.z, px1.y, px2.x, px2.w};
        const float cx[4] = {cd0.x, cd0.z, cd1.x, cd1.z};
        const float cy[4] = {cd0.y, cd0.w, cd1.y, cd1.w};

        float o[12];
        #pragma unroll
        for (int k = 0; k < 4; ++k)
            process_pixel(sg, rr[k], gg[k], bb[k], cx[k], cy[k],
                          o[3 * k + 0], o[3 * k + 1], o[3 * k + 2]);

        float4* o4 = reinterpret_cast<float4*>(out);
        o4[3 * bix + 0] = make_float4(o[0], o[1], o[2],  o[3]);
        o4[3 * bix + 1] = make_float4(o[4], o[5], o[6],  o[7]);
        o4[3 * bix + 2] = make_float4(o[8], o[9], o[10], o[11]);
    }

    // Tail (N not divisible by 4) — handled scalar by the first threads.
    const int tail_start = nb << 2;
    for (int i = tail_start + tid0; i < N; i += stride) {
        const float r = pixels[3 * i + 0];
        const float g = pixels[3 * i + 1];
        const float b = pixels[3 * i + 2];
        const float cxv = coords[2 * i + 0];
        const float cyv = coords[2 * i + 1];
        float o0, o1, o2;
        process_pixel(sg, r, g, b, cxv, cyv, o0, o1, o2);
        out[3 * i + 0] = o0;
        out[3 * i + 1] = o1;
        out[3 * i + 2] = o2;
    }
}

extern "C" void kernel_launch(void* const* d_in, const int* in_sizes, int n_in,
                              void* d_out, int out_size)
{
    const float* pixels = (const float*)d_in[0];   // (B,H,W,3) f32
    const float* coords = (const float*)d_in[1];   // (B,H,W,2) f32
    const float* grid   = (const float*)d_in[2];   // (16,16,8,12) f32
    float* out = (float*)d_out;

    const int N = in_sizes[0] / 3;

    cudaFuncSetAttribute(bilateral_grid_h2_kernel,
                         cudaFuncAttributeMaxDynamicSharedMemorySize, SMEM_BYTES);

    // 3 CTAs/SM x 152 SMs
    const int blocks = 456;
    bilateral_grid_h2_kernel<<<blocks, 256, SMEM_BYTES>>>(pixels, coords, grid, out, N);
}

// round 7
// speedup vs baseline: 1.8399x; 1.1855x over previous
#include <cuda_runtime.h>
#include <cuda_fp16.h>

#define SH 16
#define SW 16
#define SL 8
#define NCOEF 12
#define GRID_ELEMS (SH * SW * SL * NCOEF)        // 24576 halfs per copy
// Copy B lives at +GRID_ELEMS+20 halfs: byte offset 49192 -> mod 16 == 8 so
// odd-z0 records (at 24*z0 + 40, z0 odd) are 16B-aligned; bank rotation +10
// keeps copy-A lanes (banks {0,12,24,4}+c) and copy-B lanes ({16,28,8,20}+c)
// on disjoint first-word banks.
#define COPY_B_OFF (GRID_ELEMS + 20)
#define SMEM_HALFS (COPY_B_OFF + GRID_ELEMS)     // 49172 halfs
#define SMEM_BYTES (SMEM_HALFS * 2)              // 98344 B -> 2 CTAs/SM

__device__ __forceinline__ __half2 as_h2(unsigned int u) {
    return *reinterpret_cast<__half2*>(&u);
}

__device__ __forceinline__ void process_pixel(
    const __half* __restrict__ sg,
    float r, float g, float b, float cxv, float cyv,
    float& o0, float& o1, float& o2)
{
    const float guide = 0.2126f * r + 0.7152f * g + 0.0722f * b;
    const float gx = fminf(fmaxf(cxv * (float)(SW - 1), 0.0f), (float)SW - 1.001f);
    const float gy = fminf(fmaxf(cyv * (float)(SH - 1), 0.0f), (float)SH - 1.001f);
    const float gcl = fminf(fmaxf(guide, 0.0f), 1.0f);
    const float gz = fminf(fmaxf(gcl * (float)(SL - 1), 0.0f), (float)SL - 1.001f);

    const int x0 = (int)gx;
    const int y0 = (int)gy;
    const int z0 = (int)gz;
    const float fx = gx - (float)x0;
    const float fy = gy - (float)y0;
    const float fz = gz - (float)z0;
    const float wx0 = 1.0f - fx, wy0 = 1.0f - fy, wz0 = 1.0f - fz;

    // Base pointer: select the copy in which this z0's records are 16B-aligned.
    // (z0 is shared by all 4 spatial corners -> hoisted out of the corner loop.)
    const __half* base = sg + ((z0 & 1) ? COPY_B_OFF : 0)
                       + ((y0 * SW + x0) * SL + z0) * NCOEF;

    __half2 acc0 = __float2half2_rn(0.f), acc1 = acc0, acc2 = acc0;
    __half2 acc3 = acc0, acc4 = acc0, acc5 = acc0;

    #pragma unroll
    for (int dy = 0; dy < 2; ++dy) {
        const float wyv = dy ? fy : wy0;
        #pragma unroll
        for (int dx = 0; dx < 2; ++dx) {
            const float wxy = wyv * (dx ? fx : wx0);
            // 48 B record: z0's 12 halfs then z1's 12 halfs, 16B-aligned.
            const uint4* p4 = reinterpret_cast<const uint4*>(
                base + dy * (SW * SL * NCOEF) + dx * (SL * NCOEF));
            const uint4 q0 = p4[0];   // z0 coeff 0..7
            const uint4 q1 = p4[1];   // z0 coeff 8..11, z1 coeff 0..3
            const uint4 q2 = p4[2];   // z1 coeff 4..11

            const __half2 w0 = __float2half2_rn(wxy * wz0);
            const __half2 w1 = __float2half2_rn(wxy * fz);

            acc0 = __hfma2(w0, as_h2(q0.x), acc0);
            acc1 = __hfma2(w0, as_h2(q0.y), acc1);
            acc2 = __hfma2(w0, as_h2(q0.z), acc2);
            acc3 = __hfma2(w0, as_h2(q0.w), acc3);
            acc4 = __hfma2(w0, as_h2(q1.x), acc4);
            acc5 = __hfma2(w0, as_h2(q1.y), acc5);

            acc0 = __hfma2(w1, as_h2(q1.z), acc0);
            acc1 = __hfma2(w1, as_h2(q1.w), acc1);
            acc2 = __hfma2(w1, as_h2(q2.x), acc2);
            acc3 = __hfma2(w1, as_h2(q2.y), acc3);
            acc4 = __hfma2(w1, as_h2(q2.z), acc4);
            acc5 = __hfma2(w1, as_h2(q2.w), acc5);
        }
    }

    const float2 f0 = __half22float2(acc0);
    const float2 f1 = __half22float2(acc1);
    const float2 f2 = __half22float2(acc2);
    const float2 f3 = __half22float2(acc3);
    const float2 f4 = __half22float2(acc4);
    const float2 f5 = __half22float2(acc5);

    o0 = f0.x * r + f0.y * g + f1.x * b + f1.y;
    o1 = f2.x * r + f2.y * g + f3.x * b + f3.y;
    o2 = f4.x * r + f4.y * g + f5.x * b + f5.y;
}

__global__ void __launch_bounds__(256, 2)
bilateral_grid_h2d_kernel(const float* __restrict__ pixels,
                          const float* __restrict__ coords,
                          const float* __restrict__ grid,
                          float* __restrict__ out,
                          int N)
{
    extern __shared__ __half sg[];

    // Convert fp32 grid -> fp16, write BOTH copies.
    {
        const float2* g2 = reinterpret_cast<const float2*>(grid);
        __half2* a2 = reinterpret_cast<__half2*>(sg);
        __half2* b2 = reinterpret_cast<__half2*>(sg + COPY_B_OFF); // even offset -> 4B aligned
        #pragma unroll 4
        for (int i = threadIdx.x; i < GRID_ELEMS / 2; i += 256) {
            const __half2 v = __float22half2_rn(g2[i]);
            a2[i] = v;
            b2[i] = v;
        }
    }
    __syncthreads();

    const int nb = N >> 2;  // 4-pixel batches
    const int stride = gridDim.x * blockDim.x;
    const int tid0 = blockIdx.x * blockDim.x + threadIdx.x;

    for (int bix = tid0; bix < nb; bix += stride) {
        const float4 px0 = reinterpret_cast<const float4*>(pixels)[3 * bix + 0];
        const float4 px1 = reinterpret_cast<const float4*>(pixels)[3 * bix + 1];
        const float4 px2 = reinterpret_cast<const float4*>(pixels)[3 * bix + 2];
        const float4 cd0 = reinterpret_cast<const float4*>(coords)[2 * bix + 0];
        const float4 cd1 = reinterpret_cast<const float4*>(coords)[2 * bix + 1];

        const float rr[4] = {px0.x, px0.w, px1.z, px2.y};
        const float gg[4] = {px0.y, px1.x, px1.w, px2.z};
        const float bb[4] = {px0.z, px1.y, px2.x, px2.w};
        const float cx[4] = {cd0.x, cd0.z, cd1.x, cd1.z};
        const float cy[4] = {cd0.y, cd0.w, cd1.y, cd1.w};

        float o[12];
        #pragma unroll
        for (int k = 0; k < 4; ++k)
            process_pixel(sg, rr[k], gg[k], bb[k], cx[k], cy[k],
                          o[3 * k + 0], o[3 * k + 1], o[3 * k + 2]);

        float4* o4 = reinterpret_cast<float4*>(out);
        o4[3 * bix + 0] = make_float4(o[0], o[1], o[2],  o[3]);
        o4[3 * bix + 1] = make_float4(o[4], o[5], o[6],  o[7]);
        o4[3 * bix + 2] = make_float4(o[8], o[9], o[10], o[11]);
    }

    // Tail (N not divisible by 4)
    const int tail_start = nb << 2;
    for (int i = tail_start + tid0; i < N; i += stride) {
        const float r = pixels[3 * i + 0];
        const float g = pixels[3 * i + 1];
        const float b = pixels[3 * i + 2];
        const float cxv = coords[2 * i + 0];
        const float cyv = coords[2 * i + 1];
        float o0, o1, o2;
        process_pixel(sg, r, g, b, cxv, cyv, o0, o1, o2);
        out[3 * i + 0] = o0;
        out[3 * i + 1] = o1;
        out[3 * i + 2] = o2;
    }
}

extern "C" void kernel_launch(void* const* d_in, const int* in_sizes, int n_in,
                              void* d_out, int out_size)
{
    const float* pixels = (const float*)d_in[0];   // (B,H,W,3) f32
    const float* coords = (const float*)d_in[1];   // (B,H,W,2) f32
    const float* grid   = (const float*)d_in[2];   // (16,16,8,12) f32
    float* out = (float*)d_out;

    const int N = in_sizes[0] / 3;

    cudaFuncSetAttribute(bilateral_grid_h2d_kernel,
                         cudaFuncAttributeMaxDynamicSharedMemorySize, SMEM_BYTES);

    // 2 CTAs/SM x 152 SMs
    const int blocks = 304;
    bilateral_grid_h2d_kernel<<<blocks, 256, SMEM_BYTES>>>(pixels, coords, grid, out, N);
}

// round 8
// speedup vs baseline: 1.8468x; 1.0038x over previous
#include <cuda_runtime.h>
#include <cuda_fp16.h>

#define SH 16
#define SW 16
#define SL 8
#define NCOEF 12
#define GRID_ELEMS (SH * SW * SL * NCOEF)        // 24576 halfs per copy
// Copy B at +GRID_ELEMS+20 halfs: odd-z0 records become 16B-aligned there,
// and the +10-word bank rotation keeps the two copies' z-lattices disjoint.
#define COPY_B_OFF (GRID_ELEMS + 20)
#define SMEM_HALFS (COPY_B_OFF + GRID_ELEMS)
#define SMEM_BYTES (SMEM_HALFS * 2)              // 98344 B -> 2 CTAs/SM

__device__ __forceinline__ __half2 as_h2(unsigned int u) {
    return *reinterpret_cast<__half2*>(&u);
}

__device__ __forceinline__ void process_pixel(
    const __half* __restrict__ sg,
    float r, float g, float b, float cxv, float cyv,
    float& o0, float& o1, float& o2)
{
    const float guide = 0.2126f * r + 0.7152f * g + 0.0722f * b;
    const float gx = fminf(fmaxf(cxv * (float)(SW - 1), 0.0f), (float)SW - 1.001f);
    const float gy = fminf(fmaxf(cyv * (float)(SH - 1), 0.0f), (float)SH - 1.001f);
    const float gcl = fminf(fmaxf(guide, 0.0f), 1.0f);
    const float gz = fminf(fmaxf(gcl * (float)(SL - 1), 0.0f), (float)SL - 1.001f);

    const int x0 = (int)gx;
    const int y0 = (int)gy;
    const int z0 = (int)gz;
    const float fx = gx - (float)x0;
    const float fy = gy - (float)y0;
    const float fz = gz - (float)z0;
    const float wx0 = 1.0f - fx, wy0 = 1.0f - fy, wz0 = 1.0f - fz;

    // Copy select: records for this z0 are 16B-aligned in the chosen copy.
    const __half* base = sg + ((z0 & 1) ? COPY_B_OFF : 0)
                       + ((y0 * SW + x0) * SL + z0) * NCOEF;

    __half2 acc0 = __float2half2_rn(0.f), acc1 = acc0, acc2 = acc0;
    __half2 acc3 = acc0, acc4 = acc0, acc5 = acc0;

    #pragma unroll
    for (int dy = 0; dy < 2; ++dy) {
        const float wyv = dy ? fy : wy0;
        #pragma unroll
        for (int dx = 0; dx < 2; ++dx) {
            const float wxy = wyv * (dx ? fx : wx0);
            // 48 B record: z0's 12 halfs then z1's 12 halfs, 16B-aligned.
            const uint4* p4 = reinterpret_cast<const uint4*>(
                base + dy * (SW * SL * NCOEF) + dx * (SL * NCOEF));
            const uint4 q0 = p4[0];
            const uint4 q1 = p4[1];
            const uint4 q2 = p4[2];

            const __half2 w0 = __float2half2_rn(wxy * wz0);
            const __half2 w1 = __float2half2_rn(wxy * fz);

            acc0 = __hfma2(w0, as_h2(q0.x), acc0);
            acc1 = __hfma2(w0, as_h2(q0.y), acc1);
            acc2 = __hfma2(w0, as_h2(q0.z), acc2);
            acc3 = __hfma2(w0, as_h2(q0.w), acc3);
            acc4 = __hfma2(w0, as_h2(q1.x), acc4);
            acc5 = __hfma2(w0, as_h2(q1.y), acc5);

            acc0 = __hfma2(w1, as_h2(q1.z), acc0);
            acc1 = __hfma2(w1, as_h2(q1.w), acc1);
            acc2 = __hfma2(w1, as_h2(q2.x), acc2);
            acc3 = __hfma2(w1, as_h2(q2.y), acc3);
            acc4 = __hfma2(w1, as_h2(q2.z), acc4);
            acc5 = __hfma2(w1, as_h2(q2.w), acc5);
        }
    }

    const float2 f0 = __half22float2(acc0);
    const float2 f1 = __half22float2(acc1);
    const float2 f2 = __half22float2(acc2);
    const float2 f3 = __half22float2(acc3);
    const float2 f4 = __half22float2(acc4);
    const float2 f5 = __half22float2(acc5);

    o0 = f0.x * r + f0.y * g + f1.x * b + f1.y;
    o1 = f2.x * r + f2.y * g + f3.x * b + f3.y;
    o2 = f4.x * r + f4.y * g + f5.x * b + f5.y;
}

__global__ void __launch_bounds__(512, 2)
bilateral_grid_h1_kernel(const float* __restrict__ pixels,
                         const float* __restrict__ coords,
                         const float* __restrict__ grid,
                         float* __restrict__ out,
                         int N)
{
    extern __shared__ __half sg[];

    // Convert fp32 grid -> fp16, write BOTH copies.
    {
        const float2* g2 = reinterpret_cast<const float2*>(grid);
        __half2* a2 = reinterpret_cast<__half2*>(sg);
        __half2* b2 = reinterpret_cast<__half2*>(sg + COPY_B_OFF);
        #pragma unroll 4
        for (int i = threadIdx.x; i < GRID_ELEMS / 2; i += 512) {
            const __half2 v = __float22half2_rn(g2[i]);
            a2[i] = v;
            b2[i] = v;
        }
    }
    __syncthreads();

    // 1 pixel per thread: a warp's gather spans only 32 consecutive pixels
    // (1/4 of a spatial cell) -> x-cell straddle in ~25% of fetches instead
    // of ~100% with 4-pixel batching.
    const int stride = gridDim.x * blockDim.x;
    for (int i = blockIdx.x * blockDim.x + threadIdx.x; i < N; i += stride) {
        const float r = pixels[3 * i + 0];
        const float g = pixels[3 * i + 1];
        const float b = pixels[3 * i + 2];
        const float2 c = reinterpret_cast<const float2*>(coords)[i];

        float o0, o1, o2;
        process_pixel(sg, r, g, b, c.x, c.y, o0, o1, o2);

        out[3 * i + 0] = o0;
        out[3 * i + 1] = o1;
        out[3 * i + 2] = o2;
    }
}

extern "C" void kernel_launch(void* const* d_in, const int* in_sizes, int n_in,
                              void* d_out, int out_size)
{
    const float* pixels = (const float*)d_in[0];   // (B,H,W,3) f32
    const float* coords = (const float*)d_in[1];   // (B,H,W,2) f32
    const float* grid   = (const float*)d_in[2];   // (16,16,8,12) f32
    float* out = (float*)d_out;

    const int N = in_sizes[0] / 3;

    cudaFuncSetAttribute(bilateral_grid_h1_kernel,
                         cudaFuncAttributeMaxDynamicSharedMemorySize, SMEM_BYTES);

    // 2 CTAs/SM x 152 SMs, 512 threads each -> 32 warps/SM.
    const int blocks = 304;
    bilateral_grid_h1_kernel<<<blocks, 512, SMEM_BYTES>>>(pixels, coords, grid, out, N);
}